// round 7
// baseline (speedup 1.0000x reference)
#include <cuda_runtime.h>
#include <cuda_fp16.h>
#include <cstdint>

// ============================================================================
// BayesianLinear on sm_103 (base ISA — tcgen05 blocked by compute_103 target).
// fp16 single-pass GEMM (rel_err ~3e-4 < 1e-3, validated R6):
//   w = mu + softplus(rho)*eps -> fp16;  x -> fp16
//   out = x_f16 @ w_f16^T  (fp32 accum)  + bias
// R6 -> R7: warp tile 64x64 (4 warps/CTA, 2x2) — halves LDS traffic per MMA;
// 2 CTAs/SM kept; prep kernels fused into one launch.
// ============================================================================

#define IN_F   4096
#define OUT_F  4096
#define BATCH  4096

// ---------------- scratch (no cudaMalloc allowed) ----------------
__device__ __align__(16) __half g_w_h[(size_t)OUT_F * IN_F];
__device__ __align__(16) __half g_x_h[(size_t)BATCH * IN_F];
__device__ __align__(16) float  g_bias[OUT_F];

// ---------------- helpers ----------------
__device__ __forceinline__ uint32_t smem_to_u32(const void* p) {
    uint32_t a;
    asm("{ .reg .u64 t; cvta.to.shared.u64 t, %1; cvt.u32.u64 %0, t; }" : "=r"(a) : "l"(p));
    return a;
}

__device__ __forceinline__ void cp16(uint32_t saddr, const void* gptr) {
    size_t ga = __cvta_generic_to_global(gptr);
    asm volatile("cp.async.cg.shared.global [%0], [%1], 16;"
                 :: "r"(saddr), "l"(ga) : "memory");
}
#define CP_COMMIT() asm volatile("cp.async.commit_group;" ::: "memory")
#define CP_WAIT2()  asm volatile("cp.async.wait_group 2;" ::: "memory")

__device__ __forceinline__ void ldsm_x4(uint32_t (&r)[4], uint32_t saddr) {
    asm volatile("ldmatrix.sync.aligned.m8n8.x4.shared.b16 {%0,%1,%2,%3}, [%4];"
                 : "=r"(r[0]), "=r"(r[1]), "=r"(r[2]), "=r"(r[3]) : "r"(saddr));
}

__device__ __forceinline__ void mma_f16(float (&d)[4], const uint32_t (&a)[4],
                                        uint32_t b0, uint32_t b1) {
    asm volatile(
        "mma.sync.aligned.m16n8k16.row.col.f32.f16.f16.f32 "
        "{%0,%1,%2,%3}, {%4,%5,%6,%7}, {%8,%9}, {%0,%1,%2,%3};"
        : "+f"(d[0]), "+f"(d[1]), "+f"(d[2]), "+f"(d[3])
        : "r"(a[0]), "r"(a[1]), "r"(a[2]), "r"(a[3]), "r"(b0), "r"(b1));
}

__device__ __forceinline__ uint32_t pack_h2(float a, float b) {
    __half ha = __float2half_rn(a);
    __half hb = __float2half_rn(b);
    return (uint32_t)__half_as_ushort(ha) | ((uint32_t)__half_as_ushort(hb) << 16);
}

// ============================================================================
// Pass 1 (fused): weight -> fp16, x -> fp16, bias -> fp32
// blocks [0, WBLK): weight;  [WBLK, WBLK+XBLK): x;  last 16: bias
// ============================================================================
#define WBLK (OUT_F * (IN_F / 4) / 256)   // 16384
#define XBLK (BATCH * (IN_F / 4) / 256)   // 16384
#define BBLK (OUT_F / 256)                // 16

__global__ void __launch_bounds__(256) prep_kernel(
    const float* __restrict__ x,
    const float* __restrict__ wmu, const float* __restrict__ wrho,
    const float* __restrict__ bmu, const float* __restrict__ brho,
    const float* __restrict__ weps, const float* __restrict__ beps)
{
    int b = blockIdx.x;
    if (b < WBLK) {
        size_t i4 = (size_t)b * 256 + threadIdx.x;
        const float4 m = ((const float4*)wmu)[i4];
        const float4 r = ((const float4*)wrho)[i4];
        const float4 e = ((const float4*)weps)[i4];
        float w0 = m.x + (log1pf(expf(r.x)) + 1e-8f) * e.x;
        float w1 = m.y + (log1pf(expf(r.y)) + 1e-8f) * e.y;
        float w2 = m.z + (log1pf(expf(r.z)) + 1e-8f) * e.z;
        float w3 = m.w + (log1pf(expf(r.w)) + 1e-8f) * e.w;
        ((uint2*)g_w_h)[i4] = make_uint2(pack_h2(w0, w1), pack_h2(w2, w3));
    } else if (b < WBLK + XBLK) {
        size_t i4 = (size_t)(b - WBLK) * 256 + threadIdx.x;
        const float4 v = ((const float4*)x)[i4];
        ((uint2*)g_x_h)[i4] = make_uint2(pack_h2(v.x, v.y), pack_h2(v.z, v.w));
    } else {
        int i = (b - WBLK - XBLK) * 256 + threadIdx.x;
        g_bias[i] = bmu[i] + (log1pf(expf(brho[i])) + 1e-8f) * beps[i];
    }
}

// ============================================================================
// Pass 2: GEMM. CTA 128x128, BK=32 fp16, 4-stage ring, 1 sync/kt,
// 4 warps (2M x 2N, warp 64x64), 2 CTAs/SM.
// ============================================================================
#define BM 128
#define BN 128
#define BK 32
#define KPAD 40                   // fp16/row -> 80 B rows, conflict-free ldmatrix
#define ARR_B (128 * 80)          // 10240 B per array
#define OFF_A 0
#define OFF_B ARR_B
#define STAGE_BYTES (2 * ARR_B)   // 20480
#define NSTAGE 4
#define SMEM_SIZE (NSTAGE * STAGE_BYTES)   // 81920
#define NT (IN_F / BK)            // 128

__global__ void __launch_bounds__(128, 2) gemm_kernel(float* __restrict__ out)
{
    extern __shared__ char smem[];
    const uint32_t sbase = smem_to_u32(smem);
    const int tid  = threadIdx.x;
    const int lane = tid & 31;
    const int w    = tid >> 5;   // 0..3
    const int wm   = w >> 1;     // 0..1
    const int wn   = w & 1;      // 0..1
    const int m0 = blockIdx.y * BM;
    const int n0 = blockIdx.x * BN;

    float acc[4][8][4];
#pragma unroll
    for (int f = 0; f < 4; f++)
#pragma unroll
        for (int n = 0; n < 8; n++)
#pragma unroll
            for (int q = 0; q < 4; q++) acc[f][n][q] = 0.0f;

    // cp.async: thread t owns row t of both A and B tiles (4 x 16B each)
    const uint32_t lso = (uint32_t)(tid * 80);
    const size_t gxa = (size_t)(m0 + tid) * IN_F;
    const size_t gwa = (size_t)(n0 + tid) * IN_F;

    // ldmatrix fragment bases (fp16 units)
    const uint32_t a_base = (uint32_t)((wm * 64 + (lane & 15)) * KPAD + (lane >> 4) * 8);
    const uint32_t b_base = (uint32_t)((wn * 64 + (lane & 7) + ((lane >> 4) & 1) * 8) * KPAD
                                       + ((lane >> 3) & 1) * 8);

#define LOAD_STAGE(ST, KT) do {                                     \
    uint32_t sb_ = sbase + (uint32_t)(ST) * STAGE_BYTES + lso;      \
    size_t ko_ = (size_t)(KT) * BK;                                 \
    const __half* gx_ = g_x_h + gxa + ko_;                          \
    const __half* gw_ = g_w_h + gwa + ko_;                          \
    cp16(sb_ + OFF_A +  0, gx_ +  0);                               \
    cp16(sb_ + OFF_A + 16, gx_ +  8);                               \
    cp16(sb_ + OFF_A + 32, gx_ + 16);                               \
    cp16(sb_ + OFF_A + 48, gx_ + 24);                               \
    cp16(sb_ + OFF_B +  0, gw_ +  0);                               \
    cp16(sb_ + OFF_B + 16, gw_ +  8);                               \
    cp16(sb_ + OFF_B + 32, gw_ + 16);                               \
    cp16(sb_ + OFF_B + 48, gw_ + 24);                               \
} while (0)

    LOAD_STAGE(0, 0); CP_COMMIT();
    LOAD_STAGE(1, 1); CP_COMMIT();
    LOAD_STAGE(2, 2); CP_COMMIT();

#pragma unroll 2
    for (int kt = 0; kt < NT; kt++) {
        CP_WAIT2();            // stage kt%4 complete
        __syncthreads();       // publish + all warps done reading (kt-1)%4

        if (kt + 3 < NT) LOAD_STAGE((kt + 3) & 3, kt + 3);
        CP_COMMIT();           // fixed group accounting

        const uint32_t sb = sbase + (uint32_t)(kt & 3) * STAGE_BYTES;

#pragma unroll
        for (int ks = 0; ks < 2; ks++) {
            uint32_t b[4][4];
#pragma unroll
            for (int p = 0; p < 4; p++)
                ldsm_x4(b[p], sb + OFF_B + (b_base + (uint32_t)(p * 16 * KPAD + ks * 16)) * 2);
#pragma unroll
            for (int f = 0; f < 4; f++) {
                uint32_t a[4];
                ldsm_x4(a, sb + OFF_A + (a_base + (uint32_t)(f * 16 * KPAD + ks * 16)) * 2);
#pragma unroll
                for (int n = 0; n < 8; n++) {
                    const int p = n >> 1, q = (n & 1) * 2;
                    mma_f16(acc[f][n], a, b[p][q], b[p][q + 1]);
                }
            }
        }
    }

    // ---- epilogue: add bias, write out ----
#pragma unroll
    for (int n = 0; n < 8; n++) {
        const int c = n0 + wn * 64 + n * 8 + (lane & 3) * 2;
        const float2 bs = *(const float2*)(g_bias + c);
#pragma unroll
        for (int f = 0; f < 4; f++) {
            const int r = m0 + wm * 64 + f * 16 + (lane >> 2);
            float2 v0, v1;
            v0.x = acc[f][n][0] + bs.x; v0.y = acc[f][n][1] + bs.y;
            v1.x = acc[f][n][2] + bs.x; v1.y = acc[f][n][3] + bs.y;
            *(float2*)(out + (size_t)r * OUT_F + c) = v0;
            *(float2*)(out + (size_t)(r + 8) * OUT_F + c) = v1;
        }
    }
}

// ============================================================================
// launch
// ============================================================================
extern "C" void kernel_launch(void* const* d_in, const int* in_sizes, int n_in,
                              void* d_out, int out_size)
{
    const float* x    = (const float*)d_in[0];
    const float* wmu  = (const float*)d_in[1];
    const float* wrho = (const float*)d_in[2];
    const float* bmu  = (const float*)d_in[3];
    const float* brho = (const float*)d_in[4];
    const float* weps = (const float*)d_in[5];
    const float* beps = (const float*)d_in[6];
    float* out = (float*)d_out;

    prep_kernel<<<WBLK + XBLK + BBLK, 256>>>(x, wmu, wrho, bmu, brho, weps, beps);

    static bool attr_set = false;
    if (!attr_set) {
        cudaFuncSetAttribute(gemm_kernel, cudaFuncAttributeMaxDynamicSharedMemorySize, SMEM_SIZE);
        attr_set = true;
    }
    dim3 grid(OUT_F / BN, BATCH / BM);
    gemm_kernel<<<grid, 128, SMEM_SIZE>>>(out);
}

// round 9
// speedup vs baseline: 1.5484x; 1.5484x over previous
#include <cuda_runtime.h>
#include <cuda_fp16.h>
#include <cstdint>

// ============================================================================
// BayesianLinear on sm_103 (base ISA — tcgen05 blocked by compute_103 target).
// fp16 single-pass GEMM (rel_err ~3e-4 < 1e-3, validated R6):
//   w = mu + softplus(rho)*eps -> fp16;  x -> fp16
//   out = x_f16 @ w_f16^T  (fp32 accum)  + bias
// R8 -> R9: fix the cross-thread cp.async visibility race. The fragment
// prefetch of stage kt+1 now happens AFTER the wait_group + __syncthreads
// pair that publishes that stage. One barrier per kt iteration.
// ============================================================================

#define IN_F   4096
#define OUT_F  4096
#define BATCH  4096

// ---------------- scratch (no cudaMalloc allowed) ----------------
__device__ __align__(16) __half g_w_h[(size_t)OUT_F * IN_F];
__device__ __align__(16) __half g_x_h[(size_t)BATCH * IN_F];
__device__ __align__(16) float  g_bias[OUT_F];

// ---------------- helpers ----------------
__device__ __forceinline__ uint32_t smem_to_u32(const void* p) {
    uint32_t a;
    asm("{ .reg .u64 t; cvta.to.shared.u64 t, %1; cvt.u32.u64 %0, t; }" : "=r"(a) : "l"(p));
    return a;
}

__device__ __forceinline__ void cp16(uint32_t saddr, const void* gptr) {
    size_t ga = __cvta_generic_to_global(gptr);
    asm volatile("cp.async.cg.shared.global [%0], [%1], 16;"
                 :: "r"(saddr), "l"(ga) : "memory");
}
#define CP_COMMIT() asm volatile("cp.async.commit_group;" ::: "memory")
#define CP_WAIT2()  asm volatile("cp.async.wait_group 2;" ::: "memory")

__device__ __forceinline__ void ldsm_x4(uint32_t (&r)[4], uint32_t saddr) {
    asm volatile("ldmatrix.sync.aligned.m8n8.x4.shared.b16 {%0,%1,%2,%3}, [%4];"
                 : "=r"(r[0]), "=r"(r[1]), "=r"(r[2]), "=r"(r[3]) : "r"(saddr));
}

__device__ __forceinline__ void mma_f16(float (&d)[4], const uint32_t (&a)[4],
                                        uint32_t b0, uint32_t b1) {
    asm volatile(
        "mma.sync.aligned.m16n8k16.row.col.f32.f16.f16.f32 "
        "{%0,%1,%2,%3}, {%4,%5,%6,%7}, {%8,%9}, {%0,%1,%2,%3};"
        : "+f"(d[0]), "+f"(d[1]), "+f"(d[2]), "+f"(d[3])
        : "r"(a[0]), "r"(a[1]), "r"(a[2]), "r"(a[3]), "r"(b0), "r"(b1));
}

__device__ __forceinline__ uint32_t pack_h2(float a, float b) {
    __half ha = __float2half_rn(a);
    __half hb = __float2half_rn(b);
    return (uint32_t)__half_as_ushort(ha) | ((uint32_t)__half_as_ushort(hb) << 16);
}

// ============================================================================
// Pass 1 (fused): weight -> fp16, x -> fp16, bias -> fp32
// ============================================================================
#define WBLK (OUT_F * (IN_F / 4) / 256)   // 16384
#define XBLK (BATCH * (IN_F / 4) / 256)   // 16384
#define BBLK (OUT_F / 256)                // 16

__global__ void __launch_bounds__(256) prep_kernel(
    const float* __restrict__ x,
    const float* __restrict__ wmu, const float* __restrict__ wrho,
    const float* __restrict__ bmu, const float* __restrict__ brho,
    const float* __restrict__ weps, const float* __restrict__ beps)
{
    int b = blockIdx.x;
    if (b < WBLK) {
        size_t i4 = (size_t)b * 256 + threadIdx.x;
        const float4 m = ((const float4*)wmu)[i4];
        const float4 r = ((const float4*)wrho)[i4];
        const float4 e = ((const float4*)weps)[i4];
        float w0 = m.x + (log1pf(expf(r.x)) + 1e-8f) * e.x;
        float w1 = m.y + (log1pf(expf(r.y)) + 1e-8f) * e.y;
        float w2 = m.z + (log1pf(expf(r.z)) + 1e-8f) * e.z;
        float w3 = m.w + (log1pf(expf(r.w)) + 1e-8f) * e.w;
        ((uint2*)g_w_h)[i4] = make_uint2(pack_h2(w0, w1), pack_h2(w2, w3));
    } else if (b < WBLK + XBLK) {
        size_t i4 = (size_t)(b - WBLK) * 256 + threadIdx.x;
        const float4 v = ((const float4*)x)[i4];
        ((uint2*)g_x_h)[i4] = make_uint2(pack_h2(v.x, v.y), pack_h2(v.z, v.w));
    } else {
        int i = (b - WBLK - XBLK) * 256 + threadIdx.x;
        g_bias[i] = bmu[i] + (log1pf(expf(brho[i])) + 1e-8f) * beps[i];
    }
}

// ============================================================================
// Pass 2: GEMM. CTA 128x128, BK=32 fp16, 4-stage ring, 1 sync/kt,
// 8 warps (2M x 4N, warp 64x32), 2 CTAs/SM, reg-level frag double buffer.
// ============================================================================
#define BM 128
#define BN 128
#define BK 32
#define KPAD 40                   // fp16/row -> 80 B rows, conflict-free ldmatrix
#define ARR_B (128 * 80)          // 10240 B per array
#define OFF_A 0
#define OFF_B ARR_B
#define STAGE_BYTES (2 * ARR_B)   // 20480
#define NSTAGE 4
#define SMEM_SIZE (NSTAGE * STAGE_BYTES)   // 81920
#define NT (IN_F / BK)            // 128

__global__ void __launch_bounds__(256, 2) gemm_kernel(float* __restrict__ out)
{
    extern __shared__ char smem[];
    const uint32_t sbase = smem_to_u32(smem);
    const int tid  = threadIdx.x;
    const int lane = tid & 31;
    const int w    = tid >> 5;
    const int wm   = w >> 2;   // 0..1
    const int wn   = w & 3;    // 0..3
    const int m0 = blockIdx.y * BM;
    const int n0 = blockIdx.x * BN;

    float acc[4][4][4];
#pragma unroll
    for (int f = 0; f < 4; f++)
#pragma unroll
        for (int n = 0; n < 4; n++)
#pragma unroll
            for (int q = 0; q < 4; q++) acc[f][n][q] = 0.0f;

    // cp.async coords: thread t -> rows (t>>2) and (t>>2)+64; 16B chunk (t&3)
    const int lrow = tid >> 2;
    const int lc8  = (tid & 3) << 3;
    const uint32_t lso0 = (uint32_t)(lrow * 80 + lc8 * 2);
    const uint32_t lso1 = (uint32_t)((lrow + 64) * 80 + lc8 * 2);
    const size_t gx0 = (size_t)(m0 + lrow) * IN_F + lc8;
    const size_t gx1 = (size_t)(m0 + lrow + 64) * IN_F + lc8;
    const size_t gw0 = (size_t)(n0 + lrow) * IN_F + lc8;
    const size_t gw1 = (size_t)(n0 + lrow + 64) * IN_F + lc8;

    // ldmatrix fragment bases (fp16 units)
    const uint32_t a_base = (uint32_t)((wm * 64 + (lane & 15)) * KPAD + (lane >> 4) * 8);
    const uint32_t b_base = (uint32_t)((wn * 32 + (lane & 7) + ((lane >> 4) & 1) * 8) * KPAD
                                       + ((lane >> 3) & 1) * 8);

#define LOAD_STAGE(ST, KT) do {                                    \
    uint32_t sb_ = sbase + (uint32_t)(ST) * STAGE_BYTES;           \
    size_t ko_ = (size_t)(KT) * BK;                                \
    cp16(sb_ + OFF_A + lso0, g_x_h + gx0 + ko_);                   \
    cp16(sb_ + OFF_A + lso1, g_x_h + gx1 + ko_);                   \
    cp16(sb_ + OFF_B + lso0, g_w_h + gw0 + ko_);                   \
    cp16(sb_ + OFF_B + lso1, g_w_h + gw1 + ko_);                   \
} while (0)

// load fragment buffer (A: 4 f-tiles, B: 2 p-tiles) for k16 slice KS of stage SB
#define LDSM_FRAGS(AF, BF, SB, KS) do {                                            \
    uint32_t sbv_ = (SB);                                                          \
    _Pragma("unroll")                                                              \
    for (int p_ = 0; p_ < 2; p_++)                                                 \
        ldsm_x4((BF)[p_], sbv_ + OFF_B +                                           \
                (b_base + (uint32_t)(p_ * 16 * KPAD + (KS) * 16)) * 2);            \
    _Pragma("unroll")                                                              \
    for (int f_ = 0; f_ < 4; f_++)                                                 \
        ldsm_x4((AF)[f_], sbv_ + OFF_A +                                           \
                (a_base + (uint32_t)(f_ * 16 * KPAD + (KS) * 16)) * 2);            \
} while (0)

#define MMA_FRAGS(AF, BF) do {                                                     \
    _Pragma("unroll")                                                              \
    for (int f_ = 0; f_ < 4; f_++) {                                               \
        _Pragma("unroll")                                                          \
        for (int n_ = 0; n_ < 4; n_++) {                                           \
            const int p_ = n_ >> 1, q_ = (n_ & 1) * 2;                             \
            mma_f16(acc[f_][n_], (AF)[f_], (BF)[p_][q_], (BF)[p_][q_ + 1]);        \
        }                                                                          \
    }                                                                              \
} while (0)

    LOAD_STAGE(0, 0); CP_COMMIT();
    LOAD_STAGE(1, 1); CP_COMMIT();
    LOAD_STAGE(2, 2); CP_COMMIT();

    uint32_t a0[4][4], b0[2][4];   // current ks0 buffer
    uint32_t a1[4][4], b1[2][4];   // ks1 buffer

    CP_WAIT2();                    // tile 0 complete (this thread)
    __syncthreads();               // published block-wide
    LDSM_FRAGS(a0, b0, sbase, 0);  // (kt=0, ks=0)

#pragma unroll 2
    for (int kt = 0; kt < NT; kt++) {
        const uint32_t sb  = sbase + (uint32_t)(kt & 3) * STAGE_BYTES;
        const uint32_t sbn = sbase + (uint32_t)((kt + 1) & 3) * STAGE_BYTES;

        // stage kt was published by the previous iteration's barrier
        LDSM_FRAGS(a1, b1, sb, 1);           // (kt, ks=1)

        // write stage (kt+3)%4 == (kt-1)%4: its last reader finished before
        // the PREVIOUS iteration's barrier -> safe to overwrite now
        if (kt + 3 < NT) LOAD_STAGE((kt + 3) & 3, kt + 3);
        CP_COMMIT();                         // fixed group accounting

        MMA_FRAGS(a0, b0);                   // compute ks0 (hides ldsm above)

        CP_WAIT2();                          // tile kt+1 complete (this thread)
        __syncthreads();                     // publish stage kt+1 block-wide

        // prefetch (kt+1, ks=0); at kt=NT-1 reads stale-but-complete data,
        // result never used
        LDSM_FRAGS(a0, b0, sbn, 0);
        MMA_FRAGS(a1, b1);                   // compute ks1 (hides prefetch)
    }

    // ---- epilogue: add bias, write out ----
#pragma unroll
    for (int n = 0; n < 4; n++) {
        const int c = n0 + wn * 32 + n * 8 + (lane & 3) * 2;
        const float2 bs = *(const float2*)(g_bias + c);
#pragma unroll
        for (int f = 0; f < 4; f++) {
            const int r = m0 + wm * 64 + f * 16 + (lane >> 2);
            float2 v0, v1;
            v0.x = acc[f][n][0] + bs.x; v0.y = acc[f][n][1] + bs.y;
            v1.x = acc[f][n][2] + bs.x; v1.y = acc[f][n][3] + bs.y;
            *(float2*)(out + (size_t)r * OUT_F + c) = v0;
            *(float2*)(out + (size_t)(r + 8) * OUT_F + c) = v1;
        }
    }
}

// ============================================================================
// launch
// ============================================================================
extern "C" void kernel_launch(void* const* d_in, const int* in_sizes, int n_in,
                              void* d_out, int out_size)
{
    const float* x    = (const float*)d_in[0];
    const float* wmu  = (const float*)d_in[1];
    const float* wrho = (const float*)d_in[2];
    const float* bmu  = (const float*)d_in[3];
    const float* brho = (const float*)d_in[4];
    const float* weps = (const float*)d_in[5];
    const float* beps = (const float*)d_in[6];
    float* out = (float*)d_out;

    prep_kernel<<<WBLK + XBLK + BBLK, 256>>>(x, wmu, wrho, bmu, brho, weps, beps);

    static bool attr_set = false;
    if (!attr_set) {
        cudaFuncSetAttribute(gemm_kernel, cudaFuncAttributeMaxDynamicSharedMemorySize, SMEM_SIZE);
        attr_set = true;
    }
    dim3 grid(OUT_F / BN, BATCH / BM);
    gemm_kernel<<<grid, 256, SMEM_SIZE>>>(out);
}